// round 2
// baseline (speedup 1.0000x reference)
#include <cuda_runtime.h>
#include <cstdint>
#include <math.h>

#define S_   2048
#define H_   1024
#define NH_  16
#define KVH_ 4
#define HD_  64
#define E_   8
#define I_   4096

// ---------------- accurate math helpers (match XLA/libdevice) ------------------
#ifdef __FAST_MATH__
__device__ __forceinline__ float acc_expf(float x) { return (float)exp((double)x); }
__device__ __forceinline__ float acc_cosf(float x) { return (float)cos((double)x); }
__device__ __forceinline__ float acc_sinf(float x) { return (float)sin((double)x); }
__device__ __forceinline__ float acc_powf(float a, float b) { return (float)pow((double)a, (double)b); }
#else
__device__ __forceinline__ float acc_expf(float x) { return expf(x); }
__device__ __forceinline__ float acc_cosf(float x) { return cosf(x); }
__device__ __forceinline__ float acc_sinf(float x) { return sinf(x); }
__device__ __forceinline__ float acc_powf(float a, float b) { return powf(a, b); }
#endif

// TF32 rounding (same cvt.rna as cuBLAS/CUTLASS use before TF32 MMA)
__device__ __forceinline__ float tf32r(float x) {
    uint32_t u;
    asm("cvt.rna.tf32.f32 %0, %1;" : "=r"(u) : "f"(x));
    return __uint_as_float(u);
}
__device__ __forceinline__ float4 tf32r4(float4 v) {
    v.x = tf32r(v.x); v.y = tf32r(v.y); v.z = tf32r(v.z); v.w = tf32r(v.w);
    return v;
}

// ---------------- scratch (static device globals; no allocation) ----------------
__device__ float g_x1[S_*H_];          // rmsnorm1 output
__device__ float g_q[S_*H_];           // q (post-rope)
__device__ float g_k[S_*KVH_*HD_];     // k (post-rope)
__device__ float g_v[S_*KVH_*HD_];     // v
__device__ float g_att[S_*H_];         // attention output (token-major, head-concat)
__device__ float g_hidden[S_*H_];      // residual + attn out
__device__ float g_x2[S_*H_];          // rmsnorm2 output
__device__ float g_hs[S_*I_];          // shared MLP hidden
__device__ float g_hcol[(S_*2)*I_];    // expert hidden, row = assignment (t*2+slot)
__device__ float g_eo[(S_*2)*H_];      // expert output rows
__device__ int   g_cnt[E_];            // tokens per expert
__device__ int   g_list[E_*S_];        // per-expert assignment indices
__device__ float g_wts[S_*2];          // per-assignment combine weights

// ---------------- SGEMM: 128x128 tile, BK=8, 256 threads, 8x8 per thread ------
#define BM 128
#define BN 128
#define BK 8

__device__ __forceinline__ float silu_f(float v) {
    return __fdiv_rn(v, 1.0f + acc_expf(-v));
}

// EPI: 0 = plain, 1 = silu, 2 = add residual R
template<int EPI>
__global__ void __launch_bounds__(256) sgemm_k(
    const float* __restrict__ A, const float* __restrict__ B,
    float* __restrict__ C, const float* __restrict__ R,
    int M, int N, int K)
{
    __shared__ float As[BK][BM+4];
    __shared__ float Bs[BK][BN+4];
    const int tid = threadIdx.x;
    const int m0 = blockIdx.y * BM;
    const int n0 = blockIdx.x * BN;
    const int tr = (tid >> 4) * 8;
    const int tc = (tid & 15) * 8;
    const int aRow = tid >> 1;
    const int aCol = (tid & 1) * 4;
    const int bRow = tid >> 5;
    const int bCol = (tid & 31) * 4;
    const float* Ag = A + (size_t)(m0 + aRow) * K + aCol;
    const float* Bg = B + (size_t)bRow * N + (n0 + bCol);
    float acc[8][8] = {};

    for (int k0 = 0; k0 < K; k0 += BK) {
        float4 av = tf32r4(*(const float4*)(Ag + k0));
        float4 bv = tf32r4(*(const float4*)(Bg + (size_t)k0 * N));
        As[aCol+0][aRow] = av.x; As[aCol+1][aRow] = av.y;
        As[aCol+2][aRow] = av.z; As[aCol+3][aRow] = av.w;
        *(float4*)&Bs[bRow][bCol] = bv;
        __syncthreads();
        #pragma unroll
        for (int kk = 0; kk < BK; kk++) {
            float a[8], b[8];
            *(float4*)(a)   = *(const float4*)&As[kk][tr];
            *(float4*)(a+4) = *(const float4*)&As[kk][tr+4];
            *(float4*)(b)   = *(const float4*)&Bs[kk][tc];
            *(float4*)(b+4) = *(const float4*)&Bs[kk][tc+4];
            #pragma unroll
            for (int i = 0; i < 8; i++)
                #pragma unroll
                for (int j = 0; j < 8; j++)
                    acc[i][j] = __fmaf_rn(a[i], b[j], acc[i][j]);
        }
        __syncthreads();
    }

    #pragma unroll
    for (int i = 0; i < 8; i++) {
        size_t row = (size_t)(m0 + tr + i);
        float* crow = C + row * N + n0 + tc;
        #pragma unroll
        for (int j = 0; j < 8; j += 4) {
            float4 v = make_float4(acc[i][j], acc[i][j+1], acc[i][j+2], acc[i][j+3]);
            if (EPI == 1) {
                v.x = silu_f(v.x); v.y = silu_f(v.y); v.z = silu_f(v.z); v.w = silu_f(v.w);
            } else if (EPI == 2) {
                const float4 r = *(const float4*)(R + row * N + n0 + tc + j);
                v.x += r.x; v.y += r.y; v.z += r.z; v.w += r.w;
            }
            *(float4*)(crow + j) = v;
        }
    }
}

// Gathered expert GEMM. z = expert. A row = list[...]>>SHIFT, C row = list[...].
template<int EPI, int SHIFT>
__global__ void __launch_bounds__(256) sgemm_gather_k(
    const float* __restrict__ A, const float* __restrict__ Bbase,
    float* __restrict__ C,
    const int* __restrict__ list, const int* __restrict__ cnt,
    int N, int K)
{
    const int z = blockIdx.z;
    const int n = cnt[z];
    const int m0 = blockIdx.y * BM;
    if (m0 >= n) return;
    const int zoff = z * S_;
    const float* B = Bbase + (size_t)z * K * N;

    __shared__ float As[BK][BM+4];
    __shared__ float Bs[BK][BN+4];
    const int tid = threadIdx.x;
    const int n0 = blockIdx.x * BN;
    const int tr = (tid >> 4) * 8;
    const int tc = (tid & 15) * 8;
    const int aRow = tid >> 1;
    const int aCol = (tid & 1) * 4;
    const int bRow = tid >> 5;
    const int bCol = (tid & 31) * 4;

    int agRow = 0;
    if (m0 + aRow < n) agRow = list[zoff + m0 + aRow] >> SHIFT;
    const float* Ag = A + (size_t)agRow * K + aCol;
    const float* Bg = B + (size_t)bRow * N + (n0 + bCol);
    float acc[8][8] = {};

    for (int k0 = 0; k0 < K; k0 += BK) {
        float4 av = tf32r4(*(const float4*)(Ag + k0));
        float4 bv = tf32r4(*(const float4*)(Bg + (size_t)k0 * N));
        As[aCol+0][aRow] = av.x; As[aCol+1][aRow] = av.y;
        As[aCol+2][aRow] = av.z; As[aCol+3][aRow] = av.w;
        *(float4*)&Bs[bRow][bCol] = bv;
        __syncthreads();
        #pragma unroll
        for (int kk = 0; kk < BK; kk++) {
            float a[8], b[8];
            *(float4*)(a)   = *(const float4*)&As[kk][tr];
            *(float4*)(a+4) = *(const float4*)&As[kk][tr+4];
            *(float4*)(b)   = *(const float4*)&Bs[kk][tc];
            *(float4*)(b+4) = *(const float4*)&Bs[kk][tc+4];
            #pragma unroll
            for (int i = 0; i < 8; i++)
                #pragma unroll
                for (int j = 0; j < 8; j++)
                    acc[i][j] = __fmaf_rn(a[i], b[j], acc[i][j]);
        }
        __syncthreads();
    }

    #pragma unroll
    for (int i = 0; i < 8; i++) {
        int lr = m0 + tr + i;
        if (lr < n) {
            int a = list[zoff + lr];
            float* crow = C + (size_t)a * N + n0 + tc;
            #pragma unroll
            for (int j = 0; j < 8; j += 4) {
                float4 v = make_float4(acc[i][j], acc[i][j+1], acc[i][j+2], acc[i][j+3]);
                if (EPI == 1) {
                    v.x = silu_f(v.x); v.y = silu_f(v.y); v.z = silu_f(v.z); v.w = silu_f(v.w);
                }
                *(float4*)(crow + j) = v;
            }
        }
    }
}

// ---------------- RMSNorm ----------------
__global__ void rmsnorm_k(const float* __restrict__ x, const float* __restrict__ w,
                          float* __restrict__ o)
{
    const int t = blockIdx.x;
    const int tid = threadIdx.x;   // 256
    const float* xr = x + (size_t)t * H_;
    float s = 0.f;
    for (int i = tid; i < H_; i += 256) { float v = xr[i]; s = __fmaf_rn(v, v, s); }
    for (int off = 16; off; off >>= 1) s += __shfl_down_sync(0xffffffffu, s, off);
    __shared__ float red[8];
    const int wid = tid >> 5, lane = tid & 31;
    if (!lane) red[wid] = s;
    __syncthreads();
    if (tid == 0) {
        float tot = 0.f;
        #pragma unroll
        for (int i = 0; i < 8; i++) tot += red[i];
        red[0] = rsqrtf(tot * (1.0f / H_) + 1e-6f);
    }
    __syncthreads();
    const float r = red[0];
    float* orow = o + (size_t)t * H_;
    for (int i = tid; i < H_; i += 256) orow[i] = w[i] * (xr[i] * r);
}

// ---------------- RoPE (in place on q and k), matches XLA table bits ----------
__global__ void rope_k(float* __restrict__ q, float* __restrict__ k)
{
    const int idx = blockIdx.x * blockDim.x + threadIdx.x; // S*(NH+KVH)*32
    const int half = idx & 31;
    const int rest = idx >> 5;
    const int head = rest % (NH_ + KVH_);
    const int t = rest / (NH_ + KVH_);
    // XLA: inv_freq = 1 / powf(10000, j/32); ang = t * inv_freq (fp32 mul); cosf/sinf
    const float inv_freq = __fdiv_rn(1.0f, acc_powf(10000.0f, (float)half * 0.03125f));
    const float ang = __fmul_rn((float)t, inv_freq);
    const float c = acc_cosf(ang);
    const float sn = acc_sinf(ang);
    float* base = (head < NH_) ? (q + (size_t)t * H_ + head * HD_)
                               : (k + (size_t)t * (KVH_ * HD_) + (head - NH_) * HD_);
    const float x1 = base[half];
    const float x2 = base[half + 32];
    base[half]      = __fadd_rn(__fmul_rn(x1, c), -__fmul_rn(x2, sn));
    base[half + 32] = __fadd_rn(__fmul_rn(x2, c),  __fmul_rn(x1, sn));
}

// ---------------- Attention: two-pass flash, TF32-matched --------------------
// Pass 1: global max m and denominator l. Pass 2: p = tf32(exp(s-m)/l), o += p*v.
#define AQT 128
#define AKT 64
__global__ void __launch_bounds__(128) attn_k(
    const float* __restrict__ q, const float* __restrict__ k,
    const float* __restrict__ v, float* __restrict__ o)
{
    __shared__ float Ks[AKT][HD_];
    __shared__ float Vs[AKT][HD_];
    const int h = blockIdx.y;
    const int q0 = blockIdx.x * AQT;
    const int tid = threadIdx.x;
    const int qi = q0 + tid;
    const int kvh = h >> 2;   // groups = NH/KVH = 4

    const float* qrow = q + (size_t)qi * H_ + h * HD_;
    float4 qf[16];
    #pragma unroll
    for (int i = 0; i < 16; i++) qf[i] = tf32r4(*(const float4*)(qrow + i * 4));

    const int ntiles = (q0 + AQT) / AKT;
    float m = -1e30f, l = 0.f;

    // ---- pass 1: m and l ----
    for (int t = 0; t < ntiles; t++) {
        const int k0 = t * AKT;
        __syncthreads();
        for (int s2 = tid; s2 < AKT * (HD_ / 4); s2 += 128) {
            const int j = s2 >> 4, d4 = (s2 & 15) * 4;
            *(float4*)&Ks[j][d4] = tf32r4(*(const float4*)(k + (size_t)(k0 + j) * (KVH_ * HD_) + kvh * HD_ + d4));
        }
        __syncthreads();
        const int jmax = min(AKT, qi - k0 + 1);
        for (int j = 0; j < jmax; j++) {
            float s = 0.f;
            #pragma unroll
            for (int i = 0; i < 16; i++) {
                const float4 kf = *(const float4*)&Ks[j][i * 4];
                s = __fmaf_rn(qf[i].x, kf.x, s); s = __fmaf_rn(qf[i].y, kf.y, s);
                s = __fmaf_rn(qf[i].z, kf.z, s); s = __fmaf_rn(qf[i].w, kf.w, s);
            }
            s *= 0.125f;
            if (s > m) { l *= acc_expf(m - s); m = s; }
            l += acc_expf(s - m);
        }
    }

    // ---- pass 2: normalized tf32 probabilities times V ----
    float4 of[16];
    #pragma unroll
    for (int i = 0; i < 16; i++) of[i] = make_float4(0.f, 0.f, 0.f, 0.f);

    for (int t = 0; t < ntiles; t++) {
        const int k0 = t * AKT;
        __syncthreads();
        for (int s2 = tid; s2 < AKT * (HD_ / 4); s2 += 128) {
            const int j = s2 >> 4, d4 = (s2 & 15) * 4;
            *(float4*)&Ks[j][d4] = tf32r4(*(const float4*)(k + (size_t)(k0 + j) * (KVH_ * HD_) + kvh * HD_ + d4));
            *(float4*)&Vs[j][d4] = tf32r4(*(const float4*)(v + (size_t)(k0 + j) * (KVH_ * HD_) + kvh * HD_ + d4));
        }
        __syncthreads();
        const int jmax = min(AKT, qi - k0 + 1);
        for (int j = 0; j < jmax; j++) {
            float s = 0.f;
            #pragma unroll
            for (int i = 0; i < 16; i++) {
                const float4 kf = *(const float4*)&Ks[j][i * 4];
                s = __fmaf_rn(qf[i].x, kf.x, s); s = __fmaf_rn(qf[i].y, kf.y, s);
                s = __fmaf_rn(qf[i].z, kf.z, s); s = __fmaf_rn(qf[i].w, kf.w, s);
            }
            s *= 0.125f;
            const float p = tf32r(__fdiv_rn(acc_expf(s - m), l));
            #pragma unroll
            for (int i = 0; i < 16; i++) {
                const float4 vf = *(const float4*)&Vs[j][i * 4];
                of[i].x = __fmaf_rn(p, vf.x, of[i].x); of[i].y = __fmaf_rn(p, vf.y, of[i].y);
                of[i].z = __fmaf_rn(p, vf.z, of[i].z); of[i].w = __fmaf_rn(p, vf.w, of[i].w);
            }
        }
    }
    float* orow = o + (size_t)qi * H_ + h * HD_;
    #pragma unroll
    for (int i = 0; i < 16; i++) *(float4*)(orow + i * 4) = of[i];
}

// ---------------- router: logits -> softmax -> top2 -> expert lists -----------
__global__ void zero_k(int* __restrict__ c)
{
    if (threadIdx.x < E_) c[threadIdx.x] = 0;
}

__global__ void router_k(const float* __restrict__ x, const float* __restrict__ rw,
                         int* __restrict__ cnt, int* __restrict__ list,
                         float* __restrict__ wout)
{
    const int t = blockIdx.x;
    const int tid = threadIdx.x;  // 256 = 8 warps, one expert each
    const int e = tid >> 5, lane = tid & 31;
    const float* xr = x + (size_t)t * H_;
    float s = 0.f;
    for (int i = lane; i < H_; i += 32)
        s = __fmaf_rn(tf32r(xr[i]), tf32r(rw[i * E_ + e]), s);
    for (int off = 16; off; off >>= 1) s += __shfl_down_sync(0xffffffffu, s, off);
    __shared__ float logit[E_];
    if (!lane) logit[e] = s;
    __syncthreads();
    if (tid == 0) {
        float mx = logit[0];
        #pragma unroll
        for (int i = 1; i < E_; i++) mx = fmaxf(mx, logit[i]);
        float p[E_];
        #pragma unroll
        for (int i = 0; i < E_; i++) p[i] = acc_expf(logit[i] - mx);
        int i0 = 0;
        #pragma unroll
        for (int i = 1; i < E_; i++) if (p[i] > p[i0]) i0 = i;
        int i1 = (i0 == 0) ? 1 : 0;
        #pragma unroll
        for (int i = 0; i < E_; i++) if (i != i0 && p[i] > p[i1]) i1 = i;
        const float denom = p[i0] + p[i1];
        wout[2 * t + 0] = __fdiv_rn(p[i0], denom);
        wout[2 * t + 1] = __fdiv_rn(p[i1], denom);
        int pos = atomicAdd(&cnt[i0], 1);
        list[i0 * S_ + pos] = 2 * t;
        pos = atomicAdd(&cnt[i1], 1);
        list[i1 * S_ + pos] = 2 * t + 1;
    }
}

// ---------------- combine: out += w0*Eo[2t] + w1*Eo[2t+1] ----------------------
__global__ void combine_k(float* __restrict__ out, const float* __restrict__ eo,
                          const float* __restrict__ w)
{
    const int t = blockIdx.x;
    const float w0 = w[2 * t], w1 = w[2 * t + 1];
    const float* e0 = eo + (size_t)(2 * t) * H_;
    const float* e1 = eo + (size_t)(2 * t + 1) * H_;
    float* orow = out + (size_t)t * H_;
    for (int i = threadIdx.x; i < H_; i += 256)
        orow[i] += __fmaf_rn(w0, e0[i], __fmul_rn(w1, e1[i]));
}

// ---------------- host launch --------------------------------------------------
extern "C" void kernel_launch(void* const* d_in, const int* in_sizes, int n_in,
                              void* d_out, int out_size)
{
    const float* hs  = (const float*)d_in[0];
    const float* ln1 = (const float*)d_in[1];
    const float* wq  = (const float*)d_in[2];
    const float* wk  = (const float*)d_in[3];
    const float* wv  = (const float*)d_in[4];
    const float* wo  = (const float*)d_in[5];
    const float* ln2 = (const float*)d_in[6];
    const float* sw1 = (const float*)d_in[7];
    const float* sw2 = (const float*)d_in[8];
    const float* ew1 = (const float*)d_in[9];
    const float* ew2 = (const float*)d_in[10];
    const float* rw  = (const float*)d_in[11];
    float* out = (float*)d_out;

    float *x1, *q, *k, *v, *att, *hid, *x2, *hsv, *hcol, *eo, *wts;
    int *cnt, *list;
    cudaGetSymbolAddress((void**)&x1,   g_x1);
    cudaGetSymbolAddress((void**)&q,    g_q);
    cudaGetSymbolAddress((void**)&k,    g_k);
    cudaGetSymbolAddress((void**)&v,    g_v);
    cudaGetSymbolAddress((void**)&att,  g_att);
    cudaGetSymbolAddress((void**)&hid,  g_hidden);
    cudaGetSymbolAddress((void**)&x2,   g_x2);
    cudaGetSymbolAddress((void**)&hsv,  g_hs);
    cudaGetSymbolAddress((void**)&hcol, g_hcol);
    cudaGetSymbolAddress((void**)&eo,   g_eo);
    cudaGetSymbolAddress((void**)&wts,  g_wts);
    cudaGetSymbolAddress((void**)&cnt,  g_cnt);
    cudaGetSymbolAddress((void**)&list, g_list);

    // 1. rmsnorm1
    rmsnorm_k<<<S_, 256>>>(hs, ln1, x1);
    // 2. QKV projections
    sgemm_k<0><<<dim3(H_ / BN, S_ / BM), 256>>>(x1, wq, q, nullptr, S_, H_, H_);
    sgemm_k<0><<<dim3((KVH_ * HD_) / BN, S_ / BM), 256>>>(x1, wk, k, nullptr, S_, KVH_ * HD_, H_);
    sgemm_k<0><<<dim3((KVH_ * HD_) / BN, S_ / BM), 256>>>(x1, wv, v, nullptr, S_, KVH_ * HD_, H_);
    // 3. RoPE on q, k
    rope_k<<<(S_ * (NH_ + KVH_) * 32) / 256, 256>>>(q, k);
    // 4. causal GQA attention
    attn_k<<<dim3(S_ / AQT, NH_), 128>>>(q, k, v, att);
    // 5. output projection + residual
    sgemm_k<2><<<dim3(H_ / BN, S_ / BM), 256>>>(att, wo, hid, hs, S_, H_, H_);
    // 6. rmsnorm2
    rmsnorm_k<<<S_, 256>>>(hid, ln2, x2);
    // 7. router
    zero_k<<<1, 32>>>(cnt);
    router_k<<<S_, 256>>>(x2, rw, cnt, list, wts);
    // 8. shared MLP
    sgemm_k<1><<<dim3(I_ / BN, S_ / BM), 256>>>(x2, sw1, hsv, nullptr, S_, I_, H_);
    sgemm_k<2><<<dim3(H_ / BN, S_ / BM), 256>>>(hsv, sw2, out, hid, S_, H_, I_);
    // 9. gathered expert MLPs (top-2 only)
    sgemm_gather_k<1, 1><<<dim3(I_ / BN, S_ / BM, E_), 256>>>(x2, ew1, hcol, list, cnt, I_, H_);
    sgemm_gather_k<0, 0><<<dim3(H_ / BN, S_ / BM, E_), 256>>>(hcol, ew2, eo, list, cnt, H_, I_);
    // 10. combine routed experts into output
    combine_k<<<S_, 256>>>(out, eo, wts);
}

// round 3
// speedup vs baseline: 1.9898x; 1.9898x over previous
#include <cuda_runtime.h>
#include <cstdint>
#include <math.h>

#define S_   2048
#define H_   1024
#define NH_  16
#define KVH_ 4
#define HD_  64
#define E_   8
#define I_   4096

// ---------------- accurate math helpers ------------------
#ifdef __FAST_MATH__
__device__ __forceinline__ float acc_expf(float x) { return (float)exp((double)x); }
__device__ __forceinline__ float acc_cosf(float x) { return (float)cos((double)x); }
__device__ __forceinline__ float acc_sinf(float x) { return (float)sin((double)x); }
__device__ __forceinline__ float acc_powf(float a, float b) { return (float)pow((double)a, (double)b); }
#else
__device__ __forceinline__ float acc_expf(float x) { return expf(x); }
__device__ __forceinline__ float acc_cosf(float x) { return cosf(x); }
__device__ __forceinline__ float acc_sinf(float x) { return sinf(x); }
__device__ __forceinline__ float acc_powf(float a, float b) { return powf(a, b); }
#endif

// TF32 rounding (cvt.rna, same as cuBLAS pre-MMA conversion)
__device__ __forceinline__ float tf32r(float x) {
    uint32_t u;
    asm("cvt.rna.tf32.f32 %0, %1;" : "=r"(u) : "f"(x));
    return __uint_as_float(u);
}
__device__ __forceinline__ float4 tf32r4(float4 v) {
    v.x = tf32r(v.x); v.y = tf32r(v.y); v.z = tf32r(v.z); v.w = tf32r(v.w);
    return v;
}

__device__ __forceinline__ float silu_f(float v) {
    return __fdiv_rn(v, 1.0f + acc_expf(-v));
}

// ---------------- scratch ----------------
__device__ float g_x1[S_*H_];
__device__ float g_q[S_*H_];
__device__ float g_k[S_*KVH_*HD_];
__device__ float g_v[S_*KVH_*HD_];
__device__ float g_att[S_*H_];
__device__ float g_hidden[S_*H_];
__device__ float g_x2[S_*H_];
__device__ float g_hs[S_*I_];
__device__ float g_hcol[(S_*2)*I_];
__device__ float g_eo[(S_*2)*H_];
__device__ int   g_cnt[E_];
__device__ int   g_list[E_*S_];
__device__ float g_wts[S_*2];

// ---------------- TF32 tensor-core GEMM ----------------
// Block 128x128, BK=16, 256 threads = 8 warps (2m x 4n), warp tile 64x32.
// mma.sync m16n8k8 tf32, fp32 accumulate. Double-buffered smem.
#define BM  128
#define BN  128
#define BKT 16

// EPI: 0 plain, 1 silu, 2 +R residual.  GATHER: rows indirected via list.
template<int EPI, int GATHER, int SHIFT>
__global__ void __launch_bounds__(256) mma_gemm_k(
    const float* __restrict__ A, const float* __restrict__ Bbase,
    float* __restrict__ C, const float* __restrict__ R,
    const int* __restrict__ list, const int* __restrict__ cnt,
    int N, int K)
{
    int n_rows = S_;
    const float* Bz = Bbase;
    int zoff = 0;
    if (GATHER) {
        const int z = blockIdx.z;
        n_rows = cnt[z];
        if ((int)blockIdx.y * BM >= n_rows) return;
        zoff = z * S_;
        Bz = Bbase + (size_t)z * K * N;
    }

    __shared__ float As[2][BM][20];    // [m][k], stride 20: frag reads conflict-free
    __shared__ float Bs[2][BKT][136];  // [k][n], stride 136: frag reads conflict-free

    const int tid  = threadIdx.x;
    const int lane = tid & 31;
    const int wid  = tid >> 5;
    const int wm   = (wid & 1) * 64;
    const int wn   = (wid >> 1) * 32;
    const int m0   = blockIdx.y * BM;
    const int n0   = blockIdx.x * BN;

    // Global A: 2 float4/thread. idx -> row = idx/4, col4 = idx%4.
    const int aIdx0 = tid, aIdx1 = tid + 256;
    const int r0 = m0 + (aIdx0 >> 2), r1 = m0 + (aIdx1 >> 2);
    int gar0 = r0, gar1 = r1;
    if (GATHER) {
        gar0 = (r0 < n_rows) ? (list[zoff + r0] >> SHIFT) : 0;
        gar1 = (r1 < n_rows) ? (list[zoff + r1] >> SHIFT) : 0;
    }
    const float* Ag0 = A + (size_t)gar0 * K + (aIdx0 & 3) * 4;
    const float* Ag1 = A + (size_t)gar1 * K + (aIdx1 & 3) * 4;
    // Global B: 2 float4/thread. k = tid/32 (+8), col = (tid%32)*4.
    const float* Bg0 = Bz + (size_t)(tid >> 5) * N + n0 + (tid & 31) * 4;
    const float* Bg1 = Bg0 + (size_t)8 * N;

    float4 ra0, ra1, rb0, rb1;
    float acc[4][4][4] = {};

    const int nk = K / BKT;

    // prologue
    {
        ra0 = tf32r4(*(const float4*)(Ag0));
        ra1 = tf32r4(*(const float4*)(Ag1));
        rb0 = tf32r4(*(const float4*)(Bg0));
        rb1 = tf32r4(*(const float4*)(Bg1));
        *(float4*)&As[0][aIdx0 >> 2][(aIdx0 & 3) * 4] = ra0;
        *(float4*)&As[0][aIdx1 >> 2][(aIdx1 & 3) * 4] = ra1;
        *(float4*)&Bs[0][tid >> 5][(tid & 31) * 4] = rb0;
        *(float4*)&Bs[0][(tid >> 5) + 8][(tid & 31) * 4] = rb1;
        __syncthreads();
    }

    for (int c = 0; c < nk; c++) {
        const int buf = c & 1;
        if (c + 1 < nk) {
            const int k0 = (c + 1) * BKT;
            ra0 = tf32r4(*(const float4*)(Ag0 + k0));
            ra1 = tf32r4(*(const float4*)(Ag1 + k0));
            rb0 = tf32r4(*(const float4*)(Bg0 + (size_t)k0 * N));
            rb1 = tf32r4(*(const float4*)(Bg1 + (size_t)k0 * N));
        }
        // compute 2 k-steps of 8
        #pragma unroll
        for (int ks = 0; ks < 2; ks++) {
            const int kk = ks * 8 + (lane & 3);
            uint32_t a[4][4], b[4][2];
            #pragma unroll
            for (int mt = 0; mt < 4; mt++) {
                const int m = wm + mt * 16 + (lane >> 2);
                a[mt][0] = __float_as_uint(As[buf][m][kk]);
                a[mt][1] = __float_as_uint(As[buf][m + 8][kk]);
                a[mt][2] = __float_as_uint(As[buf][m][kk + 4]);
                a[mt][3] = __float_as_uint(As[buf][m + 8][kk + 4]);
            }
            #pragma unroll
            for (int nt = 0; nt < 4; nt++) {
                const int nn = wn + nt * 8 + (lane >> 2);
                b[nt][0] = __float_as_uint(Bs[buf][kk][nn]);
                b[nt][1] = __float_as_uint(Bs[buf][kk + 4][nn]);
            }
            #pragma unroll
            for (int mt = 0; mt < 4; mt++)
                #pragma unroll
                for (int nt = 0; nt < 4; nt++)
                    asm volatile(
                        "mma.sync.aligned.m16n8k8.row.col.f32.tf32.tf32.f32 "
                        "{%0,%1,%2,%3}, {%4,%5,%6,%7}, {%8,%9}, {%0,%1,%2,%3};"
                        : "+f"(acc[mt][nt][0]), "+f"(acc[mt][nt][1]),
                          "+f"(acc[mt][nt][2]), "+f"(acc[mt][nt][3])
                        : "r"(a[mt][0]), "r"(a[mt][1]), "r"(a[mt][2]), "r"(a[mt][3]),
                          "r"(b[nt][0]), "r"(b[nt][1]));
        }
        if (c + 1 < nk) {
            const int nb = buf ^ 1;
            *(float4*)&As[nb][aIdx0 >> 2][(aIdx0 & 3) * 4] = ra0;
            *(float4*)&As[nb][aIdx1 >> 2][(aIdx1 & 3) * 4] = ra1;
            *(float4*)&Bs[nb][tid >> 5][(tid & 31) * 4] = rb0;
            *(float4*)&Bs[nb][(tid >> 5) + 8][(tid & 31) * 4] = rb1;
            __syncthreads();
        }
    }

    // epilogue: c0,c1 at (row, col..col+1); c2,c3 at (row+8, col..col+1)
    #pragma unroll
    for (int mt = 0; mt < 4; mt++) {
        #pragma unroll
        for (int half = 0; half < 2; half++) {
            const int r = m0 + wm + mt * 16 + (lane >> 2) + half * 8;
            if (GATHER && r >= n_rows) continue;
            size_t crow_idx = r;
            if (GATHER) crow_idx = (size_t)list[zoff + r];
            float* crow = C + crow_idx * N;
            #pragma unroll
            for (int nt = 0; nt < 4; nt++) {
                const int col = n0 + wn + nt * 8 + (lane & 3) * 2;
                float2 v;
                v.x = acc[mt][nt][half * 2 + 0];
                v.y = acc[mt][nt][half * 2 + 1];
                if (EPI == 1) {
                    v.x = silu_f(v.x); v.y = silu_f(v.y);
                } else if (EPI == 2) {
                    const float2 rr = *(const float2*)(R + crow_idx * N + col);
                    v.x += rr.x; v.y += rr.y;
                }
                *(float2*)(crow + col) = v;
            }
        }
    }
}

// ---------------- RMSNorm ----------------
__global__ void rmsnorm_k(const float* __restrict__ x, const float* __restrict__ w,
                          float* __restrict__ o)
{
    const int t = blockIdx.x;
    const int tid = threadIdx.x;   // 256
    const float* xr = x + (size_t)t * H_;
    float s = 0.f;
    for (int i = tid; i < H_; i += 256) { float v = xr[i]; s = __fmaf_rn(v, v, s); }
    for (int off = 16; off; off >>= 1) s += __shfl_down_sync(0xffffffffu, s, off);
    __shared__ float red[8];
    const int wid = tid >> 5, lane = tid & 31;
    if (!lane) red[wid] = s;
    __syncthreads();
    if (tid == 0) {
        float tot = 0.f;
        #pragma unroll
        for (int i = 0; i < 8; i++) tot += red[i];
        red[0] = rsqrtf(tot * (1.0f / H_) + 1e-6f);
    }
    __syncthreads();
    const float r = red[0];
    float* orow = o + (size_t)t * H_;
    for (int i = tid; i < H_; i += 256) orow[i] = w[i] * (xr[i] * r);
}

// ---------------- RoPE ----------------
__global__ void rope_k(float* __restrict__ q, float* __restrict__ k)
{
    const int idx = blockIdx.x * blockDim.x + threadIdx.x; // S*(NH+KVH)*32
    const int half = idx & 31;
    const int rest = idx >> 5;
    const int head = rest % (NH_ + KVH_);
    const int t = rest / (NH_ + KVH_);
    const float inv_freq = __fdiv_rn(1.0f, acc_powf(10000.0f, (float)half * 0.03125f));
    const float ang = __fmul_rn((float)t, inv_freq);
    const float c = acc_cosf(ang);
    const float sn = acc_sinf(ang);
    float* base = (head < NH_) ? (q + (size_t)t * H_ + head * HD_)
                               : (k + (size_t)t * (KVH_ * HD_) + (head - NH_) * HD_);
    const float x1 = base[half];
    const float x2 = base[half + 32];
    base[half]      = __fadd_rn(__fmul_rn(x1, c), -__fmul_rn(x2, sn));
    base[half + 32] = __fadd_rn(__fmul_rn(x2, c),  __fmul_rn(x1, sn));
}

// ---------------- Attention: two-pass flash, TF32-matched --------------------
#define AQT 128
#define AKT 64
__global__ void __launch_bounds__(128) attn_k(
    const float* __restrict__ q, const float* __restrict__ k,
    const float* __restrict__ v, float* __restrict__ o)
{
    __shared__ float Ks[AKT][HD_];
    __shared__ float Vs[AKT][HD_];
    const int h = blockIdx.y;
    const int q0 = blockIdx.x * AQT;
    const int tid = threadIdx.x;
    const int qi = q0 + tid;
    const int kvh = h >> 2;

    const float* qrow = q + (size_t)qi * H_ + h * HD_;
    float4 qf[16];
    #pragma unroll
    for (int i = 0; i < 16; i++) qf[i] = tf32r4(*(const float4*)(qrow + i * 4));

    const int ntiles = (q0 + AQT) / AKT;
    float m = -1e30f, l = 0.f;

    for (int t = 0; t < ntiles; t++) {
        const int k0 = t * AKT;
        __syncthreads();
        for (int s2 = tid; s2 < AKT * (HD_ / 4); s2 += 128) {
            const int j = s2 >> 4, d4 = (s2 & 15) * 4;
            *(float4*)&Ks[j][d4] = tf32r4(*(const float4*)(k + (size_t)(k0 + j) * (KVH_ * HD_) + kvh * HD_ + d4));
        }
        __syncthreads();
        const int jmax = min(AKT, qi - k0 + 1);
        for (int j = 0; j < jmax; j++) {
            float s = 0.f;
            #pragma unroll
            for (int i = 0; i < 16; i++) {
                const float4 kf = *(const float4*)&Ks[j][i * 4];
                s = __fmaf_rn(qf[i].x, kf.x, s); s = __fmaf_rn(qf[i].y, kf.y, s);
                s = __fmaf_rn(qf[i].z, kf.z, s); s = __fmaf_rn(qf[i].w, kf.w, s);
            }
            s *= 0.125f;
            if (s > m) { l *= acc_expf(m - s); m = s; }
            l += acc_expf(s - m);
        }
    }

    float4 of[16];
    #pragma unroll
    for (int i = 0; i < 16; i++) of[i] = make_float4(0.f, 0.f, 0.f, 0.f);

    for (int t = 0; t < ntiles; t++) {
        const int k0 = t * AKT;
        __syncthreads();
        for (int s2 = tid; s2 < AKT * (HD_ / 4); s2 += 128) {
            const int j = s2 >> 4, d4 = (s2 & 15) * 4;
            *(float4*)&Ks[j][d4] = tf32r4(*(const float4*)(k + (size_t)(k0 + j) * (KVH_ * HD_) + kvh * HD_ + d4));
            *(float4*)&Vs[j][d4] = tf32r4(*(const float4*)(v + (size_t)(k0 + j) * (KVH_ * HD_) + kvh * HD_ + d4));
        }
        __syncthreads();
        const int jmax = min(AKT, qi - k0 + 1);
        for (int j = 0; j < jmax; j++) {
            float s = 0.f;
            #pragma unroll
            for (int i = 0; i < 16; i++) {
                const float4 kf = *(const float4*)&Ks[j][i * 4];
                s = __fmaf_rn(qf[i].x, kf.x, s); s = __fmaf_rn(qf[i].y, kf.y, s);
                s = __fmaf_rn(qf[i].z, kf.z, s); s = __fmaf_rn(qf[i].w, kf.w, s);
            }
            s *= 0.125f;
            const float p = tf32r(__fdiv_rn(acc_expf(s - m), l));
            #pragma unroll
            for (int i = 0; i < 16; i++) {
                const float4 vf = *(const float4*)&Vs[j][i * 4];
                of[i].x = __fmaf_rn(p, vf.x, of[i].x); of[i].y = __fmaf_rn(p, vf.y, of[i].y);
                of[i].z = __fmaf_rn(p, vf.z, of[i].z); of[i].w = __fmaf_rn(p, vf.w, of[i].w);
            }
        }
    }
    float* orow = o + (size_t)qi * H_ + h * HD_;
    #pragma unroll
    for (int i = 0; i < 16; i++) *(float4*)(orow + i * 4) = of[i];
}

// ---------------- router ----------------
__global__ void zero_k(int* __restrict__ c)
{
    if (threadIdx.x < E_) c[threadIdx.x] = 0;
}

__global__ void router_k(const float* __restrict__ x, const float* __restrict__ rw,
                         int* __restrict__ cnt, int* __restrict__ list,
                         float* __restrict__ wout)
{
    const int t = blockIdx.x;
    const int tid = threadIdx.x;  // 256 = 8 warps, one expert each
    const int e = tid >> 5, lane = tid & 31;
    const float* xr = x + (size_t)t * H_;
    float s = 0.f;
    for (int i = lane; i < H_; i += 32)
        s = __fmaf_rn(tf32r(xr[i]), tf32r(rw[i * E_ + e]), s);
    for (int off = 16; off; off >>= 1) s += __shfl_down_sync(0xffffffffu, s, off);
    __shared__ float logit[E_];
    if (!lane) logit[e] = s;
    __syncthreads();
    if (tid == 0) {
        float mx = logit[0];
        #pragma unroll
        for (int i = 1; i < E_; i++) mx = fmaxf(mx, logit[i]);
        float p[E_];
        #pragma unroll
        for (int i = 0; i < E_; i++) p[i] = acc_expf(logit[i] - mx);
        int i0 = 0;
        #pragma unroll
        for (int i = 1; i < E_; i++) if (p[i] > p[i0]) i0 = i;
        int i1 = (i0 == 0) ? 1 : 0;
        #pragma unroll
        for (int i = 0; i < E_; i++) if (i != i0 && p[i] > p[i1]) i1 = i;
        const float denom = p[i0] + p[i1];
        wout[2 * t + 0] = __fdiv_rn(p[i0], denom);
        wout[2 * t + 1] = __fdiv_rn(p[i1], denom);
        int pos = atomicAdd(&cnt[i0], 1);
        list[i0 * S_ + pos] = 2 * t;
        pos = atomicAdd(&cnt[i1], 1);
        list[i1 * S_ + pos] = 2 * t + 1;
    }
}

// ---------------- combine ----------------
__global__ void combine_k(float* __restrict__ out, const float* __restrict__ eo,
                          const float* __restrict__ w)
{
    const int t = blockIdx.x;
    const float w0 = w[2 * t], w1 = w[2 * t + 1];
    const float* e0 = eo + (size_t)(2 * t) * H_;
    const float* e1 = eo + (size_t)(2 * t + 1) * H_;
    float* orow = out + (size_t)t * H_;
    for (int i = threadIdx.x; i < H_; i += 256)
        orow[i] += __fmaf_rn(w0, e0[i], __fmul_rn(w1, e1[i]));
}

// ---------------- host launch --------------------------------------------------
extern "C" void kernel_launch(void* const* d_in, const int* in_sizes, int n_in,
                              void* d_out, int out_size)
{
    const float* hs  = (const float*)d_in[0];
    const float* ln1 = (const float*)d_in[1];
    const float* wq  = (const float*)d_in[2];
    const float* wk  = (const float*)d_in[3];
    const float* wv  = (const float*)d_in[4];
    const float* wo  = (const float*)d_in[5];
    const float* ln2 = (const float*)d_in[6];
    const float* sw1 = (const float*)d_in[7];
    const float* sw2 = (const float*)d_in[8];
    const float* ew1 = (const float*)d_in[9];
    const float* ew2 = (const float*)d_in[10];
    const float* rw  = (const float*)d_in[11];
    float* out = (float*)d_out;

    float *x1, *q, *k, *v, *att, *hid, *x2, *hsv, *hcol, *eo, *wts;
    int *cnt, *list;
    cudaGetSymbolAddress((void**)&x1,   g_x1);
    cudaGetSymbolAddress((void**)&q,    g_q);
    cudaGetSymbolAddress((void**)&k,    g_k);
    cudaGetSymbolAddress((void**)&v,    g_v);
    cudaGetSymbolAddress((void**)&att,  g_att);
    cudaGetSymbolAddress((void**)&hid,  g_hidden);
    cudaGetSymbolAddress((void**)&x2,   g_x2);
    cudaGetSymbolAddress((void**)&hsv,  g_hs);
    cudaGetSymbolAddress((void**)&hcol, g_hcol);
    cudaGetSymbolAddress((void**)&eo,   g_eo);
    cudaGetSymbolAddress((void**)&wts,  g_wts);
    cudaGetSymbolAddress((void**)&cnt,  g_cnt);
    cudaGetSymbolAddress((void**)&list, g_list);

    // 1. rmsnorm1
    rmsnorm_k<<<S_, 256>>>(hs, ln1, x1);
    // 2. QKV projections (tensor core)
    mma_gemm_k<0,0,0><<<dim3(H_ / BN, S_ / BM), 256>>>(x1, wq, q, nullptr, nullptr, nullptr, H_, H_);
    mma_gemm_k<0,0,0><<<dim3((KVH_ * HD_) / BN, S_ / BM), 256>>>(x1, wk, k, nullptr, nullptr, nullptr, KVH_ * HD_, H_);
    mma_gemm_k<0,0,0><<<dim3((KVH_ * HD_) / BN, S_ / BM), 256>>>(x1, wv, v, nullptr, nullptr, nullptr, KVH_ * HD_, H_);
    // 3. RoPE
    rope_k<<<(S_ * (NH_ + KVH_) * 32) / 256, 256>>>(q, k);
    // 4. attention
    attn_k<<<dim3(S_ / AQT, NH_), 128>>>(q, k, v, att);
    // 5. O-proj + residual
    mma_gemm_k<2,0,0><<<dim3(H_ / BN, S_ / BM), 256>>>(att, wo, hid, hs, nullptr, nullptr, H_, H_);
    // 6. rmsnorm2
    rmsnorm_k<<<S_, 256>>>(hid, ln2, x2);
    // 7. router
    zero_k<<<1, 32>>>(cnt);
    router_k<<<S_, 256>>>(x2, rw, cnt, list, wts);
    // 8. shared MLP
    mma_gemm_k<1,0,0><<<dim3(I_ / BN, S_ / BM), 256>>>(x2, sw1, hsv, nullptr, nullptr, nullptr, I_, H_);
    mma_gemm_k<2,0,0><<<dim3(H_ / BN, S_ / BM), 256>>>(hsv, sw2, out, hid, nullptr, nullptr, H_, I_);
    // 9. gathered expert MLPs (top-2 only)
    mma_gemm_k<1,1,1><<<dim3(I_ / BN, S_ / BM, E_), 256>>>(x2, ew1, hcol, nullptr, list, cnt, I_, H_);
    mma_gemm_k<0,1,0><<<dim3(H_ / BN, S_ / BM, E_), 256>>>(hcol, ew2, eo, nullptr, list, cnt, H_, I_);
    // 10. combine
    combine_k<<<S_, 256>>>(out, eo, wts);
}

// round 4
// speedup vs baseline: 2.8519x; 1.4333x over previous
#include <cuda_runtime.h>
#include <cstdint>
#include <math.h>

#define S_   2048
#define H_   1024
#define NH_  16
#define KVH_ 4
#define HD_  64
#define E_   8
#define I_   4096

// ---------------- accurate math helpers ------------------
#ifdef __FAST_MATH__
__device__ __forceinline__ float acc_expf(float x) { return (float)exp((double)x); }
__device__ __forceinline__ float acc_cosf(float x) { return (float)cos((double)x); }
__device__ __forceinline__ float acc_sinf(float x) { return (float)sin((double)x); }
__device__ __forceinline__ float acc_powf(float a, float b) { return (float)pow((double)a, (double)b); }
#else
__device__ __forceinline__ float acc_expf(float x) { return expf(x); }
__device__ __forceinline__ float acc_cosf(float x) { return cosf(x); }
__device__ __forceinline__ float acc_sinf(float x) { return sinf(x); }
__device__ __forceinline__ float acc_powf(float a, float b) { return powf(a, b); }
#endif

__device__ __forceinline__ float tf32r(float x) {
    uint32_t u;
    asm("cvt.rna.tf32.f32 %0, %1;" : "=r"(u) : "f"(x));
    return __uint_as_float(u);
}
__device__ __forceinline__ uint32_t tf32u(float x) {
    uint32_t u;
    asm("cvt.rna.tf32.f32 %0, %1;" : "=r"(u) : "f"(x));
    return u;
}
__device__ __forceinline__ float4 tf32r4(float4 v) {
    v.x = tf32r(v.x); v.y = tf32r(v.y); v.z = tf32r(v.z); v.w = tf32r(v.w);
    return v;
}
__device__ __forceinline__ float silu_f(float v) {
    return __fdiv_rn(v, 1.0f + acc_expf(-v));
}

__device__ __forceinline__ uint32_t s2u(const void* p) {
    return (uint32_t)__cvta_generic_to_shared(p);
}
__device__ __forceinline__ void cp16(uint32_t dst, const float* src) {
    asm volatile("cp.async.ca.shared.global [%0], [%1], 16;\n" :: "r"(dst), "l"(src));
}
__device__ __forceinline__ void cp_commit() {
    asm volatile("cp.async.commit_group;\n" ::);
}
__device__ __forceinline__ void cp_wait1() {
    asm volatile("cp.async.wait_group 1;\n" ::);
}

// ---------------- scratch ----------------
__device__ float g_x1[S_*H_];
__device__ float g_q[S_*H_];
__device__ float g_k[S_*KVH_*HD_];
__device__ float g_v[S_*KVH_*HD_];
__device__ float g_att[S_*H_];
__device__ float g_hidden[S_*H_];
__device__ float g_x2[S_*H_];
__device__ float g_hs[S_*I_];
__device__ float g_hcol[(S_*2)*I_];
__device__ float g_eo[(S_*2)*H_];
__device__ float g_sc[(size_t)NH_*S_*S_];  // cached attention scores [h][j][qi]
__device__ int   g_cnt[E_];
__device__ int   g_list[E_*S_];
__device__ float g_wts[S_*2];

// ---------------- TF32 tensor-core GEMM, 3-stage cp.async ----------------
#define BM  128
#define BN  128
#define BKT 16
#define NST 3
#define ASTR 20
#define BSTR 136
#define SMEM_GEMM ((NST*BM*ASTR + NST*BKT*BSTR) * 4)

// EPI: 0 plain, 1 silu, 2 +R.  GATHER: rows via list.  QKV: fused q/k/v proj.
template<int EPI, int GATHER, int SHIFT, int QKV>
__global__ void __launch_bounds__(256, 2) mma_gemm_k(
    const float* __restrict__ A, const float* __restrict__ B,
    float* __restrict__ C, const float* __restrict__ R,
    const int* __restrict__ list, const int* __restrict__ cnt,
    const float* __restrict__ B2, const float* __restrict__ B3,
    float* __restrict__ C2, float* __restrict__ C3,
    int N, int K)
{
    extern __shared__ float dsm[];
    float* As = dsm;                    // [NST][BM][ASTR]
    float* Bs = dsm + NST * BM * ASTR;  // [NST][BKT][BSTR]

    int n_rows = S_;
    const float* Bz = B;
    float* Cz = C;
    int zoff = 0;
    int Nl = N;
    int n0 = blockIdx.x * BN;
    if (GATHER) {
        const int z = blockIdx.z;
        n_rows = cnt[z];
        if ((int)blockIdx.y * BM >= n_rows) return;
        zoff = z * S_;
        Bz = B + (size_t)z * K * N;
    }
    if (QKV) {
        const int bx = blockIdx.x;
        if (bx < 8)       { Bz = B;  Cz = C;  Nl = 1024; n0 = bx * BN; }
        else if (bx < 10) { Bz = B2; Cz = C2; Nl = 256;  n0 = (bx - 8) * BN; }
        else              { Bz = B3; Cz = C3; Nl = 256;  n0 = (bx - 10) * BN; }
    }

    const int tid  = threadIdx.x;
    const int lane = tid & 31;
    const int wid  = tid >> 5;
    const int wm   = (wid & 1) * 64;
    const int wn   = (wid >> 1) * 32;
    const int m0   = blockIdx.y * BM;

    // A: 2 float4/thread/stage
    const int aIdx0 = tid, aIdx1 = tid + 256;
    const int r0 = m0 + (aIdx0 >> 2), r1 = m0 + (aIdx1 >> 2);
    int gar0 = r0, gar1 = r1;
    if (GATHER) {
        gar0 = (r0 < n_rows) ? (list[zoff + r0] >> SHIFT) : 0;
        gar1 = (r1 < n_rows) ? (list[zoff + r1] >> SHIFT) : 0;
    }
    const float* Ag0 = A + (size_t)gar0 * K + (aIdx0 & 3) * 4;
    const float* Ag1 = A + (size_t)gar1 * K + (aIdx1 & 3) * 4;
    // B: 2 float4/thread/stage
    const float* Bg0 = Bz + (size_t)(tid >> 5) * Nl + n0 + (tid & 31) * 4;
    const float* Bg1 = Bg0 + (size_t)8 * Nl;

    const uint32_t sa0 = s2u(&As[(size_t)(aIdx0 >> 2) * ASTR + (aIdx0 & 3) * 4]);
    const uint32_t sa1 = s2u(&As[(size_t)(aIdx1 >> 2) * ASTR + (aIdx1 & 3) * 4]);
    const uint32_t sb0 = s2u(&Bs[(size_t)(tid >> 5) * BSTR + (tid & 31) * 4]);
    const uint32_t sb1 = s2u(&Bs[(size_t)((tid >> 5) + 8) * BSTR + (tid & 31) * 4]);
    const uint32_t aStgB = BM * ASTR * 4;   // bytes per A stage
    const uint32_t bStgB = BKT * BSTR * 4;  // bytes per B stage

    float acc[4][4][4] = {};
    const int nk = K / BKT;

    auto load_stage = [&](int sbuf, int c) {
        const int k0 = c * BKT;
        cp16(sa0 + sbuf * aStgB, Ag0 + k0);
        cp16(sa1 + sbuf * aStgB, Ag1 + k0);
        cp16(sb0 + sbuf * bStgB, Bg0 + (size_t)k0 * Nl);
        cp16(sb1 + sbuf * bStgB, Bg1 + (size_t)k0 * Nl);
        cp_commit();
    };

    load_stage(0, 0);
    load_stage(1, 1);

    for (int c = 0; c < nk; c++) {
        cp_wait1();
        __syncthreads();
        const int buf = c % NST;
        if (c + NST - 1 < nk) load_stage((c + NST - 1) % NST, c + NST - 1);

        const float* Ab = As + (size_t)buf * BM * ASTR;
        const float* Bb = Bs + (size_t)buf * BKT * BSTR;
        #pragma unroll
        for (int ks = 0; ks < 2; ks++) {
            const int kk = ks * 8 + (lane & 3);
            uint32_t a[4][4], b[4][2];
            #pragma unroll
            for (int mt = 0; mt < 4; mt++) {
                const int m = wm + mt * 16 + (lane >> 2);
                a[mt][0] = tf32u(Ab[(size_t)m * ASTR + kk]);
                a[mt][1] = tf32u(Ab[(size_t)(m + 8) * ASTR + kk]);
                a[mt][2] = tf32u(Ab[(size_t)m * ASTR + kk + 4]);
                a[mt][3] = tf32u(Ab[(size_t)(m + 8) * ASTR + kk + 4]);
            }
            #pragma unroll
            for (int nt = 0; nt < 4; nt++) {
                const int nn = wn + nt * 8 + (lane >> 2);
                b[nt][0] = tf32u(Bb[(size_t)kk * BSTR + nn]);
                b[nt][1] = tf32u(Bb[(size_t)(kk + 4) * BSTR + nn]);
            }
            #pragma unroll
            for (int mt = 0; mt < 4; mt++)
                #pragma unroll
                for (int nt = 0; nt < 4; nt++)
                    asm volatile(
                        "mma.sync.aligned.m16n8k8.row.col.f32.tf32.tf32.f32 "
                        "{%0,%1,%2,%3}, {%4,%5,%6,%7}, {%8,%9}, {%0,%1,%2,%3};"
                        : "+f"(acc[mt][nt][0]), "+f"(acc[mt][nt][1]),
                          "+f"(acc[mt][nt][2]), "+f"(acc[mt][nt][3])
                        : "r"(a[mt][0]), "r"(a[mt][1]), "r"(a[mt][2]), "r"(a[mt][3]),
                          "r"(b[nt][0]), "r"(b[nt][1]));
        }
    }

    #pragma unroll
    for (int mt = 0; mt < 4; mt++) {
        #pragma unroll
        for (int half = 0; half < 2; half++) {
            const int r = m0 + wm + mt * 16 + (lane >> 2) + half * 8;
            if (GATHER && r >= n_rows) continue;
            size_t crow_idx = r;
            if (GATHER) crow_idx = (size_t)list[zoff + r];
            float* crow = Cz + crow_idx * Nl;
            #pragma unroll
            for (int nt = 0; nt < 4; nt++) {
                const int col = n0 + wn + nt * 8 + (lane & 3) * 2;
                float2 v;
                v.x = acc[mt][nt][half * 2 + 0];
                v.y = acc[mt][nt][half * 2 + 1];
                if (EPI == 1) {
                    v.x = silu_f(v.x); v.y = silu_f(v.y);
                } else if (EPI == 2) {
                    const float2 rr = *(const float2*)(R + crow_idx * Nl + col);
                    v.x += rr.x; v.y += rr.y;
                }
                *(float2*)(crow + col) = v;
            }
        }
    }
}

// ---------------- RMSNorm ----------------
__global__ void rmsnorm_k(const float* __restrict__ x, const float* __restrict__ w,
                          float* __restrict__ o)
{
    const int t = blockIdx.x;
    const int tid = threadIdx.x;   // 256
    const float* xr = x + (size_t)t * H_;
    float s = 0.f;
    for (int i = tid; i < H_; i += 256) { float v = xr[i]; s = __fmaf_rn(v, v, s); }
    for (int off = 16; off; off >>= 1) s += __shfl_down_sync(0xffffffffu, s, off);
    __shared__ float red[8];
    const int wid = tid >> 5, lane = tid & 31;
    if (!lane) red[wid] = s;
    __syncthreads();
    if (tid == 0) {
        float tot = 0.f;
        #pragma unroll
        for (int i = 0; i < 8; i++) tot += red[i];
        red[0] = rsqrtf(tot * (1.0f / H_) + 1e-6f);
    }
    __syncthreads();
    const float r = red[0];
    float* orow = o + (size_t)t * H_;
    for (int i = tid; i < H_; i += 256) orow[i] = w[i] * (xr[i] * r);
}

// ---------------- RoPE ----------------
__global__ void rope_k(float* __restrict__ q, float* __restrict__ k)
{
    const int idx = blockIdx.x * blockDim.x + threadIdx.x;
    const int half = idx & 31;
    const int rest = idx >> 5;
    const int head = rest % (NH_ + KVH_);
    const int t = rest / (NH_ + KVH_);
    const float inv_freq = __fdiv_rn(1.0f, acc_powf(10000.0f, (float)half * 0.03125f));
    const float ang = __fmul_rn((float)t, inv_freq);
    const float c = acc_cosf(ang);
    const float sn = acc_sinf(ang);
    float* base = (head < NH_) ? (q + (size_t)t * H_ + head * HD_)
                               : (k + (size_t)t * (KVH_ * HD_) + (head - NH_) * HD_);
    const float x1 = base[half];
    const float x2 = base[half + 32];
    base[half]      = __fadd_rn(__fmul_rn(x1, c), -__fmul_rn(x2, sn));
    base[half + 32] = __fadd_rn(__fmul_rn(x2, c),  __fmul_rn(x1, sn));
}

// ---------------- Attention: two-pass flash + score cache --------------------
#define AQT 128
#define AKT 64
__global__ void __launch_bounds__(128) attn_k(
    const float* __restrict__ q, const float* __restrict__ k,
    const float* __restrict__ v, float* __restrict__ o,
    float* __restrict__ sc)
{
    __shared__ union SU {
        float Ks[AKT][HD_];   // pass 1
        float Ss[AKT][AQT];   // pass 2
    } su;
    __shared__ float Vs[AKT][HD_];

    const int h = blockIdx.y;
    const int q0 = blockIdx.x * AQT;
    const int tid = threadIdx.x;
    const int qi = q0 + tid;
    const int kvh = h >> 2;
    const size_t hS = (size_t)h * S_;

    const float* qrow = q + (size_t)qi * H_ + h * HD_;
    float4 qf[16];
    #pragma unroll
    for (int i = 0; i < 16; i++) qf[i] = tf32r4(*(const float4*)(qrow + i * 4));

    const int ntiles = (q0 + AQT) / AKT;
    float m = -1e30f, l = 0.f;

    // ---- pass 1: scores -> gmem cache, running m/l ----
    for (int t = 0; t < ntiles; t++) {
        const int k0 = t * AKT;
        __syncthreads();
        for (int s2 = tid; s2 < AKT * (HD_ / 4); s2 += 128) {
            const int j = s2 >> 4, d4 = (s2 & 15) * 4;
            *(float4*)&su.Ks[j][d4] = tf32r4(*(const float4*)(k + (size_t)(k0 + j) * (KVH_ * HD_) + kvh * HD_ + d4));
        }
        __syncthreads();
        const int jmax = min(AKT, qi - k0 + 1);
        for (int j = 0; j < jmax; j++) {
            float s = 0.f;
            #pragma unroll
            for (int i = 0; i < 16; i++) {
                const float4 kf = *(const float4*)&su.Ks[j][i * 4];
                s = __fmaf_rn(qf[i].x, kf.x, s); s = __fmaf_rn(qf[i].y, kf.y, s);
                s = __fmaf_rn(qf[i].z, kf.z, s); s = __fmaf_rn(qf[i].w, kf.w, s);
            }
            s *= 0.125f;
            sc[(hS + (k0 + j)) * S_ + qi] = s;
            if (s > m) { l *= acc_expf(m - s); m = s; }
            l += acc_expf(s - m);
        }
    }

    // ---- pass 2: read cached scores, normalized tf32 p, accumulate V ----
    float4 of[16];
    #pragma unroll
    for (int i = 0; i < 16; i++) of[i] = make_float4(0.f, 0.f, 0.f, 0.f);

    for (int t = 0; t < ntiles; t++) {
        const int k0 = t * AKT;
        __syncthreads();
        for (int s2 = tid; s2 < AKT * (HD_ / 4); s2 += 128) {
            const int j = s2 >> 4, d4 = (s2 & 15) * 4;
            *(float4*)&Vs[j][d4] = tf32r4(*(const float4*)(v + (size_t)(k0 + j) * (KVH_ * HD_) + kvh * HD_ + d4));
        }
        // stage this tile's scores: [j][qlocal], coalesced
        for (int s2 = tid; s2 < AKT * (AQT / 4); s2 += 128) {
            const int j = s2 >> 5, c4 = (s2 & 31) * 4;
            *(float4*)&su.Ss[j][c4] = *(const float4*)(sc + (hS + (k0 + j)) * S_ + q0 + c4);
        }
        __syncthreads();
        const int jmax = min(AKT, qi - k0 + 1);
        #pragma unroll 4
        for (int j = 0; j < jmax; j++) {
            const float s = su.Ss[j][tid];
            const float p = tf32r(__fdiv_rn(acc_expf(s - m), l));
            #pragma unroll
            for (int i = 0; i < 16; i++) {
                const float4 vf = *(const float4*)&Vs[j][i * 4];
                of[i].x = __fmaf_rn(p, vf.x, of[i].x); of[i].y = __fmaf_rn(p, vf.y, of[i].y);
                of[i].z = __fmaf_rn(p, vf.z, of[i].z); of[i].w = __fmaf_rn(p, vf.w, of[i].w);
            }
        }
    }
    float* orow = o + (size_t)qi * H_ + h * HD_;
    #pragma unroll
    for (int i = 0; i < 16; i++) *(float4*)(orow + i * 4) = of[i];
}

// ---------------- router ----------------
__global__ void zero_k(int* __restrict__ c)
{
    if (threadIdx.x < E_) c[threadIdx.x] = 0;
}

__global__ void router_k(const float* __restrict__ x, const float* __restrict__ rw,
                         int* __restrict__ cnt, int* __restrict__ list,
                         float* __restrict__ wout)
{
    const int t = blockIdx.x;
    const int tid = threadIdx.x;
    const int e = tid >> 5, lane = tid & 31;
    const float* xr = x + (size_t)t * H_;
    float s = 0.f;
    for (int i = lane; i < H_; i += 32)
        s = __fmaf_rn(tf32r(xr[i]), tf32r(rw[i * E_ + e]), s);
    for (int off = 16; off; off >>= 1) s += __shfl_down_sync(0xffffffffu, s, off);
    __shared__ float logit[E_];
    if (!lane) logit[e] = s;
    __syncthreads();
    if (tid == 0) {
        float mx = logit[0];
        #pragma unroll
        for (int i = 1; i < E_; i++) mx = fmaxf(mx, logit[i]);
        float p[E_];
        #pragma unroll
        for (int i = 0; i < E_; i++) p[i] = acc_expf(logit[i] - mx);
        int i0 = 0;
        #pragma unroll
        for (int i = 1; i < E_; i++) if (p[i] > p[i0]) i0 = i;
        int i1 = (i0 == 0) ? 1 : 0;
        #pragma unroll
        for (int i = 0; i < E_; i++) if (i != i0 && p[i] > p[i1]) i1 = i;
        const float denom = p[i0] + p[i1];
        wout[2 * t + 0] = __fdiv_rn(p[i0], denom);
        wout[2 * t + 1] = __fdiv_rn(p[i1], denom);
        int pos = atomicAdd(&cnt[i0], 1);
        list[i0 * S_ + pos] = 2 * t;
        pos = atomicAdd(&cnt[i1], 1);
        list[i1 * S_ + pos] = 2 * t + 1;
    }
}

// ---------------- combine ----------------
__global__ void combine_k(float* __restrict__ out, const float* __restrict__ eo,
                          const float* __restrict__ w)
{
    const int t = blockIdx.x;
    const float w0 = w[2 * t], w1 = w[2 * t + 1];
    const float* e0 = eo + (size_t)(2 * t) * H_;
    const float* e1 = eo + (size_t)(2 * t + 1) * H_;
    float* orow = out + (size_t)t * H_;
    for (int i = threadIdx.x; i < H_; i += 256)
        orow[i] += __fmaf_rn(w0, e0[i], __fmul_rn(w1, e1[i]));
}

// ---------------- host launch --------------------------------------------------
extern "C" void kernel_launch(void* const* d_in, const int* in_sizes, int n_in,
                              void* d_out, int out_size)
{
    const float* hs  = (const float*)d_in[0];
    const float* ln1 = (const float*)d_in[1];
    const float* wq  = (const float*)d_in[2];
    const float* wk  = (const float*)d_in[3];
    const float* wv  = (const float*)d_in[4];
    const float* wo  = (const float*)d_in[5];
    const float* ln2 = (const float*)d_in[6];
    const float* sw1 = (const float*)d_in[7];
    const float* sw2 = (const float*)d_in[8];
    const float* ew1 = (const float*)d_in[9];
    const float* ew2 = (const float*)d_in[10];
    const float* rw  = (const float*)d_in[11];
    float* out = (float*)d_out;

    float *x1, *q, *k, *v, *att, *hid, *x2, *hsv, *hcol, *eo, *wts, *sc;
    int *cnt, *list;
    cudaGetSymbolAddress((void**)&x1,   g_x1);
    cudaGetSymbolAddress((void**)&q,    g_q);
    cudaGetSymbolAddress((void**)&k,    g_k);
    cudaGetSymbolAddress((void**)&v,    g_v);
    cudaGetSymbolAddress((void**)&att,  g_att);
    cudaGetSymbolAddress((void**)&hid,  g_hidden);
    cudaGetSymbolAddress((void**)&x2,   g_x2);
    cudaGetSymbolAddress((void**)&hsv,  g_hs);
    cudaGetSymbolAddress((void**)&hcol, g_hcol);
    cudaGetSymbolAddress((void**)&eo,   g_eo);
    cudaGetSymbolAddress((void**)&wts,  g_wts);
    cudaGetSymbolAddress((void**)&sc,   g_sc);
    cudaGetSymbolAddress((void**)&cnt,  g_cnt);
    cudaGetSymbolAddress((void**)&list, g_list);

    // allow >48KB dynamic smem for the GEMM instantiations (idempotent)
    cudaFuncSetAttribute(mma_gemm_k<0,0,0,1>, cudaFuncAttributeMaxDynamicSharedMemorySize, SMEM_GEMM);
    cudaFuncSetAttribute(mma_gemm_k<2,0,0,0>, cudaFuncAttributeMaxDynamicSharedMemorySize, SMEM_GEMM);
    cudaFuncSetAttribute(mma_gemm_k<1,0,0,0>, cudaFuncAttributeMaxDynamicSharedMemorySize, SMEM_GEMM);
    cudaFuncSetAttribute(mma_gemm_k<1,1,1,0>, cudaFuncAttributeMaxDynamicSharedMemorySize, SMEM_GEMM);
    cudaFuncSetAttribute(mma_gemm_k<0,1,0,0>, cudaFuncAttributeMaxDynamicSharedMemorySize, SMEM_GEMM);

    // 1. rmsnorm1
    rmsnorm_k<<<S_, 256>>>(hs, ln1, x1);
    // 2. fused QKV projection
    mma_gemm_k<0,0,0,1><<<dim3(12, S_ / BM), 256, SMEM_GEMM>>>(
        x1, wq, q, nullptr, nullptr, nullptr, wk, wv, k, v, H_, H_);
    // 3. RoPE
    rope_k<<<(S_ * (NH_ + KVH_) * 32) / 256, 256>>>(q, k);
    // 4. attention (two-pass with score cache)
    attn_k<<<dim3(S_ / AQT, NH_), 128>>>(q, k, v, att, sc);
    // 5. O-proj + residual
    mma_gemm_k<2,0,0,0><<<dim3(H_ / BN, S_ / BM), 256, SMEM_GEMM>>>(
        att, wo, hid, hs, nullptr, nullptr, nullptr, nullptr, nullptr, nullptr, H_, H_);
    // 6. rmsnorm2
    rmsnorm_k<<<S_, 256>>>(hid, ln2, x2);
    // 7. router
    zero_k<<<1, 32>>>(cnt);
    router_k<<<S_, 256>>>(x2, rw, cnt, list, wts);
    // 8. shared MLP
    mma_gemm_k<1,0,0,0><<<dim3(I_ / BN, S_ / BM), 256, SMEM_GEMM>>>(
        x2, sw1, hsv, nullptr, nullptr, nullptr, nullptr, nullptr, nullptr, nullptr, I_, H_);
    mma_gemm_k<2,0,0,0><<<dim3(H_ / BN, S_ / BM), 256, SMEM_GEMM>>>(
        hsv, sw2, out, hid, nullptr, nullptr, nullptr, nullptr, nullptr, nullptr, H_, I_);
    // 9. gathered expert MLPs (top-2 only)
    mma_gemm_k<1,1,1,0><<<dim3(I_ / BN, S_ / BM, E_), 256, SMEM_GEMM>>>(
        x2, ew1, hcol, nullptr, list, cnt, nullptr, nullptr, nullptr, nullptr, I_, H_);
    mma_gemm_k<0,1,0,0><<<dim3(H_ / BN, S_ / BM, E_), 256, SMEM_GEMM>>>(
        hcol, ew2, eo, nullptr, list, cnt, nullptr, nullptr, nullptr, nullptr, H_, I_);
    // 10. combine
    combine_k<<<S_, 256>>>(out, eo, wts);
}